// round 12
// baseline (speedup 1.0000x reference)
#include <cuda_runtime.h>
#include <cstdint>

#define BB 4
#define HH 16
#define SSEQ 2048
#define DDIM 64
#define OUT_O_ELEMS ((size_t)BB * HH * SSEQ * DDIM)

#define KC 64
#define NCH (SSEQ / KC)       // 32
#define STQ 68                // Q/K smem stride (floats)
#define STV 72                // V smem stride (floats)

// SMEM: KS0|KS1 (2 x 64 x STQ) | VS0|VS1 (2 x 64 x STV) | liS(128)
#define SMEM_FLOATS (2 * KC * STQ + 2 * KC * STV + 128)
#define SMEM_BYTES (SMEM_FLOATS * 4)    // 72192 B -> 3 CTAs/SM

__device__ int g_maskFlag = 0;

__device__ __forceinline__ uint32_t f2tf32(float x) {
    uint32_t r;
    asm("cvt.rna.tf32.f32 %0, %1;" : "=r"(r) : "f"(x));
    return r;
}
__device__ __forceinline__ float tf(float x) { return __uint_as_float(f2tf32(x)); }

__device__ __forceinline__ void mma_tf32(float* c,
                                         uint32_t a0, uint32_t a1, uint32_t a2, uint32_t a3,
                                         uint32_t b0, uint32_t b1) {
    asm volatile(
        "mma.sync.aligned.m16n8k8.row.col.f32.tf32.tf32.f32 "
        "{%0,%1,%2,%3}, {%4,%5,%6,%7}, {%8,%9}, {%0,%1,%2,%3};"
        : "+f"(c[0]), "+f"(c[1]), "+f"(c[2]), "+f"(c[3])
        : "r"(a0), "r"(a1), "r"(a2), "r"(a3), "r"(b0), "r"(b1));
}

__global__ void mask_check(const float* __restrict__ mask, size_t n) {
    size_t i = (size_t)blockIdx.x * blockDim.x + threadIdx.x;
    uint32_t any = 0;
    const size_t stride = (size_t)gridDim.x * blockDim.x;
    for (; i < n; i += stride) any |= __float_as_uint(mask[i]);
    if (__any_sync(0xffffffffu, any != 0u) && (threadIdx.x & 31) == 0)
        atomicOr(&g_maskFlag, 1);
}

// ============================================================
// Single-pass fused attention. 128 q-rows/CTA, 4 warps (32 x KC warp tile).
// Phase A: per chunk: s = QK^T(+mask); e = exp(s) -> gmem (unnormalized);
//          l += e; e(tf32) -> A-frag via shuffles; PV mma accumulates O.
// Epilogue: O *= 1/l.
// Phase B: re-stream own e-strip, w = e * (1/l) in place (coalesced).
// Prefetch: 4-stage staggered half-chunk loads (16 regs live).
// ============================================================
__global__ __launch_bounds__(128, 3)
void attn_fused(const float* __restrict__ q, const float* __restrict__ k,
                const float* __restrict__ v, const float* __restrict__ mask,
                float* __restrict__ out) {
    extern __shared__ float sm[];
    float* KS0 = sm;                        // 64 x STQ
    float* KS1 = KS0 + KC * STQ;
    float* VS0 = KS1 + KC * STQ;            // 64 x STV
    float* VS1 = VS0 + KC * STV;
    float* liS = VS1 + KC * STV;            // 128

    const int tid = threadIdx.x;
    const int warp = tid >> 5, lane = tid & 31;
    const int grp = lane >> 2, tid4 = lane & 3;
    const int mt = blockIdx.x, bh = blockIdx.y;
    const int q0 = mt * 128;
    const int m0 = warp * 32;
    const size_t base = (size_t)bh * SSEQ * DDIM;
    const int mflag = *(volatile int*)&g_maskFlag;

    const int sl0 = (lane & 28) + (tid4 >> 1);   // shuffle src lanes for C->A frag
    const int sl1 = sl0 + 2;
    const bool odd = (tid4 & 1);

    // ---- stage Q (pre-scaled 1/8, tf32) in two 64-row half-tiles via KS0 ----
    float qa[2][8][4];
    #pragma unroll
    for (int half = 0; half < 2; half++) {
        const float4* qg = (const float4*)(q + base + (size_t)(q0 + half * 64) * DDIM);
        #pragma unroll
        for (int it = 0; it < 8; it++) {
            int j = tid + it * 128;
            int row = j >> 4, c = (j & 15) * 4;
            float4 v4 = qg[j];
            KS0[row * STQ + c]     = tf(v4.x * 0.125f);
            KS0[row * STQ + c + 1] = tf(v4.y * 0.125f);
            KS0[row * STQ + c + 2] = tf(v4.z * 0.125f);
            KS0[row * STQ + c + 3] = tf(v4.w * 0.125f);
        }
        __syncthreads();
        if ((m0 >> 6) == half) {
            const int r0b = m0 & 63;
            #pragma unroll
            for (int mf = 0; mf < 2; mf++) {
                const int r0 = r0b + mf * 16 + grp;
                #pragma unroll
                for (int kk = 0; kk < 8; kk++) {
                    qa[mf][kk][0] = KS0[r0 * STQ + kk * 8 + tid4];
                    qa[mf][kk][1] = KS0[(r0 + 8) * STQ + kk * 8 + tid4];
                    qa[mf][kk][2] = KS0[r0 * STQ + kk * 8 + tid4 + 4];
                    qa[mf][kk][3] = KS0[(r0 + 8) * STQ + kk * 8 + tid4 + 4];
                }
            }
        }
        __syncthreads();
    }

    // ---- stage K0 and V0 (full 64-row chunks) ----
    {
        const float4* kg = (const float4*)(k + base);
        const float4* vg = (const float4*)(v + base);
        #pragma unroll
        for (int i = 0; i < 8; i++) {
            int idx = tid + i * 128;
            int row = idx >> 4, c = (idx & 15) * 4;
            float4 a = kg[idx];
            *(float4*)&KS0[row * STQ + c] = make_float4(tf(a.x), tf(a.y), tf(a.z), tf(a.w));
            float4 b = vg[idx];
            *(float4*)&VS0[row * STV + c] = make_float4(tf(b.x), tf(b.y), tf(b.z), tf(b.w));
        }
    }
    __syncthreads();

    // ================= Phase A: single pass =================
    float l[2][2] = {};
    float o[2][8][4] = {};
    float* wb = out + OUT_O_ELEMS + (size_t)bh * SSEQ * SSEQ + (size_t)q0 * SSEQ;

    for (int c = 0; c < NCH; c++) {
        float* kcur = (c & 1) ? KS1 : KS0;
        float* knxt = (c & 1) ? KS0 : KS1;
        float* vcur = (c & 1) ? VS1 : VS0;
        float* vnxt = (c & 1) ? VS0 : VS1;
        const float4* kg1 = (const float4*)(k + base + (size_t)(c + 1) * KC * DDIM);
        const float4* vg1 = (const float4*)(v + base + (size_t)(c + 1) * KC * DDIM);
        const bool more = (c + 1 < NCH);

        // prefetch stage 1: K rows 0..31 of next chunk
        float4 pf[4];
        if (more) {
            #pragma unroll
            for (int i = 0; i < 4; i++) pf[i] = kg1[tid + i * 128];
        }

        #pragma unroll
        for (int fn = 0; fn < 8; fn++) {
            // --- QK^T for this 8-col block ---
            float s[2][4] = {};
            #pragma unroll
            for (int kk = 0; kk < 8; kk++) {
                uint32_t b0 = __float_as_uint(kcur[(fn * 8 + grp) * STQ + kk * 8 + tid4]);
                uint32_t b1 = __float_as_uint(kcur[(fn * 8 + grp) * STQ + kk * 8 + tid4 + 4]);
                mma_tf32(s[0], __float_as_uint(qa[0][kk][0]), __float_as_uint(qa[0][kk][1]),
                               __float_as_uint(qa[0][kk][2]), __float_as_uint(qa[0][kk][3]), b0, b1);
                mma_tf32(s[1], __float_as_uint(qa[1][kk][0]), __float_as_uint(qa[1][kk][1]),
                               __float_as_uint(qa[1][kk][2]), __float_as_uint(qa[1][kk][3]), b0, b1);
            }
            #pragma unroll
            for (int mf = 0; mf < 2; mf++) {
                const int r0 = m0 + mf * 16 + grp;
                if (mflag) {
                    const float* mr0 = mask + (size_t)(q0 + r0) * SSEQ + c * KC + fn * 8 + tid4 * 2;
                    const float* mr1 = mr0 + 8 * SSEQ;
                    float2 v0 = *(const float2*)mr0;
                    float2 v1 = *(const float2*)mr1;
                    s[mf][0] += v0.x; s[mf][1] += v0.y; s[mf][2] += v1.x; s[mf][3] += v1.y;
                }
                float e0 = __expf(s[mf][0]), e1 = __expf(s[mf][1]);
                float e2 = __expf(s[mf][2]), e3 = __expf(s[mf][3]);
                l[mf][0] += e0 + e1;
                l[mf][1] += e2 + e3;

                // store unnormalized e (32B sector-complete per row)
                float* w0 = wb + (size_t)r0 * SSEQ + c * KC + fn * 8 + tid4 * 2;
                *(float2*)w0 = make_float2(e0, e1);
                *(float2*)(w0 + 8 * SSEQ) = make_float2(e2, e3);

                // C-frag -> A-frag via shuffles
                float x0 = __shfl_sync(0xffffffffu, e0, sl0);
                float x1 = __shfl_sync(0xffffffffu, e1, sl0);
                float x2 = __shfl_sync(0xffffffffu, e2, sl0);
                float x3 = __shfl_sync(0xffffffffu, e3, sl0);
                float y0 = __shfl_sync(0xffffffffu, e0, sl1);
                float y1 = __shfl_sync(0xffffffffu, e1, sl1);
                float y2 = __shfl_sync(0xffffffffu, e2, sl1);
                float y3 = __shfl_sync(0xffffffffu, e3, sl1);
                uint32_t a0 = f2tf32(odd ? x1 : x0);
                uint32_t a1 = f2tf32(odd ? x3 : x2);
                uint32_t a2 = f2tf32(odd ? y1 : y0);
                uint32_t a3 = f2tf32(odd ? y3 : y2);

                // P·V accumulate
                #pragma unroll
                for (int nb = 0; nb < 8; nb++) {
                    uint32_t b0 = __float_as_uint(vcur[(fn * 8 + tid4) * STV + nb * 8 + grp]);
                    uint32_t b1 = __float_as_uint(vcur[(fn * 8 + tid4 + 4) * STV + nb * 8 + grp]);
                    mma_tf32(o[mf][nb], a0, a1, a2, a3, b0, b1);
                }
            }

            // ---- 4-stage staggered prefetch (full 64-row chunks) ----
            if (more) {
                if (fn == 1) {            // store K rows 0..31; fetch K rows 32..63
                    #pragma unroll
                    for (int i = 0; i < 4; i++) {
                        int idx = tid + i * 128;
                        int row = idx >> 4, cc = (idx & 15) * 4;
                        *(float4*)&knxt[row * STQ + cc] =
                            make_float4(tf(pf[i].x), tf(pf[i].y), tf(pf[i].z), tf(pf[i].w));
                    }
                    #pragma unroll
                    for (int i = 0; i < 4; i++) pf[i] = kg1[tid + (i + 4) * 128];
                } else if (fn == 3) {     // store K rows 32..63; fetch V rows 0..31
                    #pragma unroll
                    for (int i = 0; i < 4; i++) {
                        int idx = tid + (i + 4) * 128;
                        int row = idx >> 4, cc = (idx & 15) * 4;
                        *(float4*)&knxt[row * STQ + cc] =
                            make_float4(tf(pf[i].x), tf(pf[i].y), tf(pf[i].z), tf(pf[i].w));
                    }
                    #pragma unroll
                    for (int i = 0; i < 4; i++) pf[i] = vg1[tid + i * 128];
                } else if (fn == 5) {     // store V rows 0..31; fetch V rows 32..63
                    #pragma unroll
                    for (int i = 0; i < 4; i++) {
                        int idx = tid + i * 128;
                        int row = idx >> 4, cc = (idx & 15) * 4;
                        *(float4*)&vnxt[row * STV + cc] =
                            make_float4(tf(pf[i].x), tf(pf[i].y), tf(pf[i].z), tf(pf[i].w));
                    }
                    #pragma unroll
                    for (int i = 0; i < 4; i++) pf[i] = vg1[tid + (i + 4) * 128];
                }
            }
        }
        // store V rows 32..63
        if (more) {
            #pragma unroll
            for (int i = 0; i < 4; i++) {
                int idx = tid + (i + 4) * 128;
                int row = idx >> 4, cc = (idx & 15) * 4;
                *(float4*)&vnxt[row * STV + cc] =
                    make_float4(tf(pf[i].x), tf(pf[i].y), tf(pf[i].z), tf(pf[i].w));
            }
        }
        __syncthreads();
    }

    // ---- reduce l -> li; publish to liS; scale + write O ----
    float li[2][2];
    #pragma unroll
    for (int mf = 0; mf < 2; mf++)
        #pragma unroll
        for (int i = 0; i < 2; i++) {
            float x = l[mf][i];
            x += __shfl_xor_sync(0xffffffffu, x, 1);
            x += __shfl_xor_sync(0xffffffffu, x, 2);
            li[mf][i] = 1.f / x;
            if (tid4 == 0) liS[m0 + mf * 16 + grp + i * 8] = li[mf][i];
        }

    float* ob = out + base + (size_t)q0 * DDIM;
    #pragma unroll
    for (int mf = 0; mf < 2; mf++) {
        const int r0 = m0 + mf * 16 + grp;
        #pragma unroll
        for (int nb = 0; nb < 8; nb++) {
            int col = nb * 8 + tid4 * 2;
            *(float2*)&ob[(size_t)r0 * DDIM + col] =
                make_float2(o[mf][nb][0] * li[mf][0], o[mf][nb][1] * li[mf][0]);
            *(float2*)&ob[(size_t)(r0 + 8) * DDIM + col] =
                make_float2(o[mf][nb][2] * li[mf][1], o[mf][nb][3] * li[mf][1]);
        }
    }
    __syncthreads();   // liS visible to all

    // ================= Phase B: normalize own weights strip =================
    #pragma unroll 4
    for (int i = 0; i < 512; i++) {
        int idx = tid + i * 128;
        int row = idx >> 9;                 // 512 float4 per row
        int c4 = (idx & 511) * 4;
        float4* gp = (float4*)(wb + (size_t)row * SSEQ + c4);
        float4 e4 = *gp;
        float lir = liS[row];
        *gp = make_float4(e4.x * lir, e4.y * lir, e4.z * lir, e4.w * lir);
    }
}

extern "C" void kernel_launch(void* const* d_in, const int* in_sizes, int n_in,
                              void* d_out, int out_size) {
    const float* q    = (const float*)d_in[0];
    const float* k    = (const float*)d_in[1];
    const float* v    = (const float*)d_in[2];
    const float* mask = (const float*)d_in[3];
    float* out = (float*)d_out;

    cudaFuncSetAttribute(attn_fused, cudaFuncAttributeMaxDynamicSharedMemorySize, SMEM_BYTES);

    mask_check<<<1024, 256>>>(mask, (size_t)SSEQ * SSEQ);
    attn_fused<<<dim3(16, BB * HH), 128, SMEM_BYTES>>>(q, k, v, mask, out);
}

// round 14
// speedup vs baseline: 1.6601x; 1.6601x over previous
#include <cuda_runtime.h>
#include <cstdint>

#define BB 4
#define HH 16
#define SSEQ 2048
#define DDIM 64
#define OUT_O_ELEMS ((size_t)BB * HH * SSEQ * DDIM)

#define KC 64
#define NCH (SSEQ / KC)       // 32
#define STK 68                // K smem stride (floats)
#define STV 72                // V smem stride (floats)

// SMEM: kA 64xSTK | kB 64xSTV | liS(128). Q stages over kA+kB region first.
#define SMEM_FLOATS (KC * STK + KC * STV + 128)
#define SMEM_BYTES (SMEM_FLOATS * 4)          // 36352 B -> 3 CTAs/SM

__device__ int g_maskFlag = 0;

__device__ __forceinline__ uint32_t f2tf32(float x) {
    uint32_t r;
    asm("cvt.rna.tf32.f32 %0, %1;" : "=r"(r) : "f"(x));
    return r;
}
__device__ __forceinline__ float tf(float x) { return __uint_as_float(f2tf32(x)); }

__device__ __forceinline__ void mma_tf32(float* c,
                                         uint32_t a0, uint32_t a1, uint32_t a2, uint32_t a3,
                                         uint32_t b0, uint32_t b1) {
    asm volatile(
        "mma.sync.aligned.m16n8k8.row.col.f32.tf32.tf32.f32 "
        "{%0,%1,%2,%3}, {%4,%5,%6,%7}, {%8,%9}, {%0,%1,%2,%3};"
        : "+f"(c[0]), "+f"(c[1]), "+f"(c[2]), "+f"(c[3])
        : "r"(a0), "r"(a1), "r"(a2), "r"(a3), "r"(b0), "r"(b1));
}

__global__ void mask_check(const float* __restrict__ mask, size_t n) {
    size_t i = (size_t)blockIdx.x * blockDim.x + threadIdx.x;
    uint32_t any = 0;
    const size_t stride = (size_t)gridDim.x * blockDim.x;
    for (; i < n; i += stride) any |= __float_as_uint(mask[i]);
    if (__any_sync(0xffffffffu, any != 0u) && (threadIdx.x & 31) == 0)
        atomicOr(&g_maskFlag, 1);
}

// ============================================================
// Single-pass fused attention, spill-free. 128 q-rows/CTA, 4 warps.
// Per chunk (synchronous staging, single-buffered — R4 pass-2 structure):
//   s = QK^T (+mask); e = exp(s) -> gmem (unnormalized); l += e;
//   e -> A-frag via shuffles; PV mma accumulates O.
// Epilogue: O *= 1/l. Phase B: w = e * (1/l) in place, coalesced.
// ============================================================
__global__ __launch_bounds__(128, 3)
void attn_onepass(const float* __restrict__ q, const float* __restrict__ k,
                  const float* __restrict__ v, const float* __restrict__ mask,
                  float* __restrict__ out) {
    extern __shared__ float sm[];
    float* kA  = sm;                       // 64 x STK
    float* kB  = sm + KC * STK;            // 64 x STV
    float* liS = kB + KC * STV;            // 128

    const int tid = threadIdx.x;
    const int warp = tid >> 5, lane = tid & 31;
    const int grp = lane >> 2, tid4 = lane & 3;
    const int mt = blockIdx.x, bh = blockIdx.y;
    const int q0 = mt * 128;
    const int m0 = warp * 32;
    const size_t base = (size_t)bh * SSEQ * DDIM;
    const int mflag = *(volatile int*)&g_maskFlag;

    const int sl0 = (lane & 28) + (tid4 >> 1);   // C->A frag shuffle src lanes
    const int sl1 = sl0 + 2;
    const bool odd = (tid4 & 1);

    // ---- stage Q (pre-scaled 1/8, tf32) over the kA/kB region ----
    {
        const float4* qg = (const float4*)(q + base + (size_t)q0 * DDIM);
        #pragma unroll
        for (int it = 0; it < 16; it++) {
            int j = tid + it * 128;
            int row = j >> 4, c = (j & 15) * 4;
            float4 v4 = qg[j];
            sm[row * STK + c]     = tf(v4.x * 0.125f);
            sm[row * STK + c + 1] = tf(v4.y * 0.125f);
            sm[row * STK + c + 2] = tf(v4.z * 0.125f);
            sm[row * STK + c + 3] = tf(v4.w * 0.125f);
        }
    }
    __syncthreads();

    // ---- gather Q A-fragments into registers ----
    float qa[2][8][4];
    #pragma unroll
    for (int mf = 0; mf < 2; mf++) {
        const int r0 = m0 + mf * 16 + grp;
        #pragma unroll
        for (int kk = 0; kk < 8; kk++) {
            qa[mf][kk][0] = sm[r0 * STK + kk * 8 + tid4];
            qa[mf][kk][1] = sm[(r0 + 8) * STK + kk * 8 + tid4];
            qa[mf][kk][2] = sm[r0 * STK + kk * 8 + tid4 + 4];
            qa[mf][kk][3] = sm[(r0 + 8) * STK + kk * 8 + tid4 + 4];
        }
    }

    float l[2][2] = {};
    float o[2][8][4] = {};
    float* wb = out + OUT_O_ELEMS + (size_t)bh * SSEQ * SSEQ + (size_t)q0 * SSEQ;

    for (int c = 0; c < NCH; c++) {
        __syncthreads();   // previous chunk fully consumed (c=0: qa gather done)
        {
            const float4* kg = (const float4*)(k + base + (size_t)c * KC * DDIM);
            const float4* vg = (const float4*)(v + base + (size_t)c * KC * DDIM);
            #pragma unroll
            for (int i = 0; i < 8; i++) {
                int idx = tid + i * 128;
                int row = idx >> 4, cc = (idx & 15) * 4;
                float4 a = kg[idx];
                kA[row * STK + cc]     = tf(a.x);
                kA[row * STK + cc + 1] = tf(a.y);
                kA[row * STK + cc + 2] = tf(a.z);
                kA[row * STK + cc + 3] = tf(a.w);
                float4 b = vg[idx];
                kB[row * STV + cc]     = tf(b.x);
                kB[row * STV + cc + 1] = tf(b.y);
                kB[row * STV + cc + 2] = tf(b.z);
                kB[row * STV + cc + 3] = tf(b.w);
            }
        }
        __syncthreads();

        #pragma unroll
        for (int fn = 0; fn < 8; fn++) {
            // --- QK^T for this 8-col block ---
            float s[2][4] = {};
            #pragma unroll
            for (int kk = 0; kk < 8; kk++) {
                uint32_t b0 = __float_as_uint(kA[(fn * 8 + grp) * STK + kk * 8 + tid4]);
                uint32_t b1 = __float_as_uint(kA[(fn * 8 + grp) * STK + kk * 8 + tid4 + 4]);
                mma_tf32(s[0], __float_as_uint(qa[0][kk][0]), __float_as_uint(qa[0][kk][1]),
                               __float_as_uint(qa[0][kk][2]), __float_as_uint(qa[0][kk][3]), b0, b1);
                mma_tf32(s[1], __float_as_uint(qa[1][kk][0]), __float_as_uint(qa[1][kk][1]),
                               __float_as_uint(qa[1][kk][2]), __float_as_uint(qa[1][kk][3]), b0, b1);
            }

            #pragma unroll
            for (int mf = 0; mf < 2; mf++) {
                const int r0 = m0 + mf * 16 + grp;
                if (mflag) {
                    const float* mr0 = mask + (size_t)(q0 + r0) * SSEQ + c * KC + fn * 8 + tid4 * 2;
                    const float* mr1 = mr0 + 8 * SSEQ;
                    float2 v0 = *(const float2*)mr0;
                    float2 v1 = *(const float2*)mr1;
                    s[mf][0] += v0.x; s[mf][1] += v0.y; s[mf][2] += v1.x; s[mf][3] += v1.y;
                }
                float e0 = __expf(s[mf][0]), e1 = __expf(s[mf][1]);
                float e2 = __expf(s[mf][2]), e3 = __expf(s[mf][3]);
                l[mf][0] += e0 + e1;
                l[mf][1] += e2 + e3;

                // store unnormalized e (32B sector-complete per row)
                float* w0 = wb + (size_t)r0 * SSEQ + c * KC + fn * 8 + tid4 * 2;
                *(float2*)w0 = make_float2(e0, e1);
                *(float2*)(w0 + 8 * SSEQ) = make_float2(e2, e3);

                // C-frag -> A-frag via shuffles (no smem round trip)
                float x0 = __shfl_sync(0xffffffffu, e0, sl0);
                float x1 = __shfl_sync(0xffffffffu, e1, sl0);
                float x2 = __shfl_sync(0xffffffffu, e2, sl0);
                float x3 = __shfl_sync(0xffffffffu, e3, sl0);
                float y0 = __shfl_sync(0xffffffffu, e0, sl1);
                float y1 = __shfl_sync(0xffffffffu, e1, sl1);
                float y2 = __shfl_sync(0xffffffffu, e2, sl1);
                float y3 = __shfl_sync(0xffffffffu, e3, sl1);
                uint32_t a0 = f2tf32(odd ? x1 : x0);
                uint32_t a1 = f2tf32(odd ? x3 : x2);
                uint32_t a2 = f2tf32(odd ? y1 : y0);
                uint32_t a3 = f2tf32(odd ? y3 : y2);

                // P·V accumulate
                #pragma unroll
                for (int nb = 0; nb < 8; nb++) {
                    uint32_t b0 = __float_as_uint(kB[(fn * 8 + tid4) * STV + nb * 8 + grp]);
                    uint32_t b1 = __float_as_uint(kB[(fn * 8 + tid4 + 4) * STV + nb * 8 + grp]);
                    mma_tf32(o[mf][nb], a0, a1, a2, a3, b0, b1);
                }
            }
        }
    }

    // ---- reduce l -> li; publish; scale + write O ----
    float li[2][2];
    #pragma unroll
    for (int mf = 0; mf < 2; mf++)
        #pragma unroll
        for (int i = 0; i < 2; i++) {
            float x = l[mf][i];
            x += __shfl_xor_sync(0xffffffffu, x, 1);
            x += __shfl_xor_sync(0xffffffffu, x, 2);
            li[mf][i] = 1.f / x;
            if (tid4 == 0) liS[m0 + mf * 16 + grp + i * 8] = li[mf][i];
        }

    float* ob = out + base + (size_t)q0 * DDIM;
    #pragma unroll
    for (int mf = 0; mf < 2; mf++) {
        const int r0 = m0 + mf * 16 + grp;
        #pragma unroll
        for (int nb = 0; nb < 8; nb++) {
            int col = nb * 8 + tid4 * 2;
            *(float2*)&ob[(size_t)r0 * DDIM + col] =
                make_float2(o[mf][nb][0] * li[mf][0], o[mf][nb][1] * li[mf][0]);
            *(float2*)&ob[(size_t)(r0 + 8) * DDIM + col] =
                make_float2(o[mf][nb][2] * li[mf][1], o[mf][nb][3] * li[mf][1]);
        }
    }
    __syncthreads();   // liS visible to all warps

    // ---- Phase B: normalize own 128-row weights strip (coalesced RMW) ----
    #pragma unroll 8
    for (int i = 0; i < 512; i++) {
        int idx = tid + i * 128;
        int row = idx >> 9;                 // 512 float4 per row
        int c4 = (idx & 511) * 4;
        float4* gp = (float4*)(wb + (size_t)row * SSEQ + c4);
        float4 e4 = *gp;
        float lir = liS[row];
        *gp = make_float4(e4.x * lir, e4.y * lir, e4.z * lir, e4.w * lir);
    }
}

extern "C" void kernel_launch(void* const* d_in, const int* in_sizes, int n_in,
                              void* d_out, int out_size) {
    const float* q    = (const float*)d_in[0];
    const float* k    = (const float*)d_in[1];
    const float* v    = (const float*)d_in[2];
    const float* mask = (const float*)d_in[3];
    float* out = (float*)d_out;

    cudaFuncSetAttribute(attn_onepass, cudaFuncAttributeMaxDynamicSharedMemorySize, SMEM_BYTES);

    mask_check<<<2048, 256>>>(mask, (size_t)SSEQ * SSEQ);
    attn_onepass<<<dim3(16, BB * HH), 128, SMEM_BYTES>>>(q, k, v, mask, out);
}